// round 16
// baseline (speedup 1.0000x reference)
#include <cuda_runtime.h>
#include <cuda_bf16.h>
#include <cstddef>
#include <cstdint>

// ---------------------------------------------------------------------------
// PoseNetX_LIGHT: conv7x7/s16 -> relu -> avgpool -> fc -> {node head, edge head}
// Edge GEMM algebraically factored:  edge = relu(A1[n1] + A2[n2]).
// R16: GEMM cp.async pipeline deepened to 4 stages (3 tiles in flight,
//      wait_group 2, unconditional commit for tail correctness).
//      Conv / heads / split unchanged from R15.
// ---------------------------------------------------------------------------

#define NN 256        // nodes
#define NE 8192       // edges
#define HW 256
#define CO 512
#define KK 147        // 3*7*7
#define KPAD 160      // 10 ksteps of 16
#define KPITCH 168    // conv smem row pitch (elems)
#define FEAT 2048

// -------- scratch (no allocations allowed) --------
__device__ float g_A1[NN * FEAT];        // node @ W1^T + proj_b
__device__ float g_A2[NN * FEAT];        // node @ W2^T
__device__ int   g_n1[NE];
__device__ int   g_n2[NE];
__device__ __nv_bfloat16 g_wbf_hi[CO * KPITCH];   // conv weights hi (smem image)
__device__ __nv_bfloat16 g_wbf_lo[CO * KPITCH];   // conv weights lo
__device__ __nv_bfloat16 g_feat_hi[NN * CO];      // pooled features hi
__device__ __nv_bfloat16 g_feat_lo[NN * CO];      // pooled features lo
__device__ __nv_bfloat16 g_node_hi[NN * FEAT];    // fc output hi
__device__ __nv_bfloat16 g_node_lo[NN * FEAT];    // fc output lo
__device__ __nv_bfloat16 g_fcw_hi[FEAT * CO];     // fc_w hi
__device__ __nv_bfloat16 g_fcw_lo[FEAT * CO];     // fc_w lo
__device__ __nv_bfloat16 g_pw_hi[FEAT * 2 * FEAT];  // proj_w hi
__device__ __nv_bfloat16 g_pw_lo[FEAT * 2 * FEAT];  // proj_w lo

// -------- warp-mma helpers (sm_80+ ISA; valid on plain sm_100) --------
__device__ __forceinline__ uint32_t smem_u32(const void* p) {
    uint32_t a;
    asm("{ .reg .u64 t; cvta.to.shared.u64 t, %1; cvt.u32.u64 %0, t; }"
        : "=r"(a) : "l"(p));
    return a;
}
__device__ __forceinline__ void ldm_x4(uint32_t& r0, uint32_t& r1,
                                       uint32_t& r2, uint32_t& r3, uint32_t addr) {
    asm volatile("ldmatrix.sync.aligned.m8n8.x4.shared.b16 {%0,%1,%2,%3}, [%4];"
                 : "=r"(r0), "=r"(r1), "=r"(r2), "=r"(r3) : "r"(addr));
}
__device__ __forceinline__ void mma_bf16(float* c, const uint32_t* a,
                                         uint32_t b0, uint32_t b1) {
    asm volatile(
        "mma.sync.aligned.m16n8k16.row.col.f32.bf16.bf16.f32 "
        "{%0,%1,%2,%3}, {%4,%5,%6,%7}, {%8,%9}, {%0,%1,%2,%3};"
        : "+f"(c[0]), "+f"(c[1]), "+f"(c[2]), "+f"(c[3])
        : "r"(a[0]), "r"(a[1]), "r"(a[2]), "r"(a[3]), "r"(b0), "r"(b1));
}
#define CP16(dst, src) \
    asm volatile("cp.async.ca.shared.global [%0], [%1], 16;" \
                 :: "r"(dst), "l"(src) : "memory")
#define CP_COMMIT() asm volatile("cp.async.commit_group;" ::: "memory")
#define CP_WAIT0()  asm volatile("cp.async.wait_group 0;" ::: "memory")
#define CP_WAIT2()  asm volatile("cp.async.wait_group 2;" ::: "memory")

__device__ __forceinline__ void split_bf16(float v, __nv_bfloat16& h,
                                           __nv_bfloat16& l) {
    h = __float2bfloat16(v);
    l = __float2bfloat16(v - __bfloat162float(h));
}

// conv smem byte layout
#define SM_POOL 0
#define SM_LUT  2048
#define TILE_B  (128 * KPITCH * 2)
#define SM_AHI  4096
#define SM_ALO  (SM_AHI + TILE_B)
#define SM_BHI  (SM_ALO + TILE_B)
#define SM_BLO  (SM_BHI + TILE_B)
#define SM_CONV_TOTAL (SM_BLO + TILE_B)     // 176128 B

// ---------------------------------------------------------------------------
// K0: normalize edge_index (auto-detect int32 vs int64), n1=min, n2=max
// ---------------------------------------------------------------------------
__global__ void edge_prep_kernel(const void* __restrict__ ei_raw) {
    __shared__ int nz;
    int tid = threadIdx.x;
    if (tid == 0) nz = 0;
    __syncthreads();
    const int* w32 = (const int*)ei_raw;
    if (tid < 64 && w32[2 * tid + 1] != 0) atomicOr(&nz, 1);
    __syncthreads();
    if (nz == 0) {
        const long long* e = (const long long*)ei_raw;
        for (int i = tid; i < NE; i += 256) {
            int u = (int)e[i], v = (int)e[NE + i];
            g_n1[i] = min(u, v);
            g_n2[i] = max(u, v);
        }
    } else {
        const int* e = w32;
        for (int i = tid; i < NE; i += 256) {
            int u = e[i], v = e[NE + i];
            g_n1[i] = min(u, v);
            g_n2[i] = max(u, v);
        }
    }
}

// ---------------------------------------------------------------------------
// K1: split ALL weights (conv + fc + proj) into bf16 hi/lo in one kernel.
// ---------------------------------------------------------------------------
__global__ void wsplit_all_kernel(const float* __restrict__ conv_w,
                                  const float* __restrict__ fcw,
                                  const float* __restrict__ pw) {
    const int NCV = CO * KPAD;              // 81920
    const int NFC = FEAT * CO;              // 1048576
    const int NPW = FEAT * 2 * FEAT;        // 8388608
    for (int i = blockIdx.x * 256 + threadIdx.x; i < NCV + NFC + NPW;
         i += gridDim.x * 256) {
        if (i < NCV) {
            int ch = i / KPAD;
            int k  = i - ch * KPAD;
            float v = (k < KK) ? conv_w[(size_t)ch * KK + k] : 0.f;
            split_bf16(v, g_wbf_hi[(size_t)ch * KPITCH + k],
                       g_wbf_lo[(size_t)ch * KPITCH + k]);
        } else if (i < NCV + NFC) {
            int j = i - NCV;
            split_bf16(fcw[j], g_fcw_hi[j], g_fcw_lo[j]);
        } else {
            int j = i - NCV - NFC;
            split_bf16(pw[j], g_pw_hi[j], g_pw_lo[j]);
        }
    }
}

// ---------------------------------------------------------------------------
// K2: conv + bias + relu + avgpool via warp mma, one block per node.
// (unchanged from R15)
// ---------------------------------------------------------------------------
__global__ void __launch_bounds__(512, 1)
conv_mma_kernel(const float* __restrict__ x, const float* __restrict__ cbias) {
    extern __shared__ __align__(16) char smem[];
    float* pool_s = (float*)(smem + SM_POOL);
    int* kyL = (int*)(smem + SM_LUT);
    int* kxL = kyL + KPAD;
    int* cbL = kxL + KPAD;
    const uint32_t smb = smem_u32(smem);
    const int tid  = threadIdx.x;
    const int lane = tid & 31;
    const int w    = tid >> 5;
    const int wm   = w & 3;
    const int wn   = w >> 2;
    const int n    = blockIdx.x;

    pool_s[tid < 512 ? tid : 0] = 0.f;
    if (tid < KPAD) {
        if (tid < KK) {
            int ci = tid / 49;
            int r7 = tid - ci * 49;
            kyL[tid] = r7 / 7;
            kxL[tid] = r7 - (r7 / 7) * 7;
            cbL[tid] = ci * 65536;
        } else {
            kyL[tid] = -100000;
            kxL[tid] = 0;
            cbL[tid] = 0;
        }
    }

    const uint32_t aoff = (uint32_t)(((lane & 7) + ((lane >> 3) & 1) * 8) * KPITCH
                                     + (lane >> 4) * 8) * 2u;
    const uint32_t boff = (uint32_t)(((lane & 7) + ((lane >> 4) & 1) * 8) * KPITCH
                                     + ((lane >> 3) & 1) * 8) * 2u;

    const float* xb = x + (size_t)n * (3 * HW * HW);

    for (int half = 0; half < 2; half++) {
        __syncthreads();
        for (int e = tid; e < 128 * KPAD; e += 512) {
            int r = e / KPAD;
            int k = e - r * KPAD;
            int p  = half * 128 + r;
            int oy = p >> 4, ox = p & 15;
            int iy = oy * 16 - 3 + kyL[k];
            int ix = ox * 16 - 3 + kxL[k];
            float v = 0.f;
            if ((unsigned)iy < 256u && (unsigned)ix < 256u)
                v = __ldg(&xb[cbL[k] + iy * 256 + ix]);
            __nv_bfloat16 hi, lo;
            split_bf16(v, hi, lo);
            uint32_t o = (uint32_t)(r * KPITCH + k) * 2u;
            *(__nv_bfloat16*)(smem + SM_BHI + o) = hi;
            *(__nv_bfloat16*)(smem + SM_BLO + o) = lo;
        }

        for (int mt = 0; mt < 4; mt++) {
            __syncthreads();
            {
                const char* srcH = (const char*)(g_wbf_hi + (size_t)mt * 128 * KPITCH);
                const char* srcL = (const char*)(g_wbf_lo + (size_t)mt * 128 * KPITCH);
                const int cnt = 128 * KPITCH * 2 / 16;
                for (int i = tid; i < cnt; i += 512) {
                    CP16(smb + SM_AHI + 16 * i, srcH + 16 * i);
                    CP16(smb + SM_ALO + 16 * i, srcL + 16 * i);
                }
                CP_COMMIT();
                CP_WAIT0();
            }
            __syncthreads();

            float acc[2][4][4];
#pragma unroll
            for (int mf = 0; mf < 2; mf++)
#pragma unroll
                for (int nf = 0; nf < 4; nf++)
#pragma unroll
                    for (int i = 0; i < 4; i++) acc[mf][nf][i] = 0.f;

            const uint32_t awarp = (uint32_t)(wm * 32 * KPITCH) * 2u;
            const uint32_t bwarp = (uint32_t)(wn * 32 * KPITCH) * 2u;
#pragma unroll 1
            for (int pass = 0; pass < 3; pass++) {
                const uint32_t Ab = smb + (pass == 2 ? SM_ALO : SM_AHI) + awarp + aoff;
                const uint32_t Bb = smb + (pass == 1 ? SM_BLO : SM_BHI) + bwarp + boff;
#pragma unroll
                for (int ks = 0; ks < 10; ks++) {
                    const uint32_t ko = (uint32_t)ks * 32u;
                    uint32_t a[2][4];
                    ldm_x4(a[0][0], a[0][1], a[0][2], a[0][3], Ab + ko);
                    ldm_x4(a[1][0], a[1][1], a[1][2], a[1][3],
                           Ab + ko + 16u * KPITCH * 2u);
                    uint32_t b[4][2];
                    ldm_x4(b[0][0], b[0][1], b[1][0], b[1][1], Bb + ko);
                    ldm_x4(b[2][0], b[2][1], b[3][0], b[3][1],
                           Bb + ko + 16u * KPITCH * 2u);
#pragma unroll
                    for (int mf = 0; mf < 2; mf++)
#pragma unroll
                        for (int nf = 0; nf < 4; nf++)
                            mma_bf16(acc[mf][nf], a[mf], b[nf][0], b[nf][1]);
                }
            }

#pragma unroll
            for (int mf = 0; mf < 2; mf++) {
                int ch = mt * 128 + wm * 32 + mf * 16 + (lane >> 2);
                float b0 = __ldg(&cbias[ch]);
                float b1 = __ldg(&cbias[ch + 8]);
                float p0 = 0.f, p1 = 0.f;
#pragma unroll
                for (int nf = 0; nf < 4; nf++) {
                    p0 += fmaxf(acc[mf][nf][0] + b0, 0.f)
                        + fmaxf(acc[mf][nf][1] + b0, 0.f);
                    p1 += fmaxf(acc[mf][nf][2] + b1, 0.f)
                        + fmaxf(acc[mf][nf][3] + b1, 0.f);
                }
                p0 += __shfl_xor_sync(0xffffffffu, p0, 1);
                p0 += __shfl_xor_sync(0xffffffffu, p0, 2);
                p1 += __shfl_xor_sync(0xffffffffu, p1, 1);
                p1 += __shfl_xor_sync(0xffffffffu, p1, 2);
                if ((lane & 3) == 0) {
                    int c0 = mt * 128 + wm * 32 + mf * 16 + (lane >> 2);
                    atomicAdd(&pool_s[c0], p0);
                    atomicAdd(&pool_s[c0 + 8], p1);
                }
            }
        }
    }

    __syncthreads();
    {
        float v = pool_s[tid] * (1.0f / 256.0f);
        __nv_bfloat16 hi, lo;
        split_bf16(v, hi, lo);
        g_feat_hi[n * CO + tid] = hi;
        g_feat_lo[n * CO + tid] = lo;
    }
}

// ---------------------------------------------------------------------------
// K3: NT GEMM via bf16 mma (hi/lo 3-pass), pre-split operands.
// 4-stage cp.async ring (3 tiles in flight, wait_group 2).
// Block 128M x 64N, 512 threads. K%64==0, ktiles >= 2.
// ---------------------------------------------------------------------------
struct GemmJobB {
    const __nv_bfloat16* Bhi;
    const __nv_bfloat16* Blo;
    const float* bias;
    float* C;             // optional fp32 output
    __nv_bfloat16* Chi;   // optional hi/lo outputs
    __nv_bfloat16* Clo;
};

#define GBK 64
#define GPITCH 72
#define GASZ (128 * GPITCH * 2)
#define GBSZ (64 * GPITCH * 2)
#define GBUF (2 * GASZ + 2 * GBSZ)         // 55296 B
#define NSTAGE 4
#define GSM_TOTAL (NSTAGE * GBUF)          // 221184 B

__global__ void __launch_bounds__(512, 1)
gemm_mma_kernel(const __nv_bfloat16* __restrict__ Ahi,
                const __nv_bfloat16* __restrict__ Alo, int lda,
                GemmJobB j0, GemmJobB j1, int ldb, int ldc, int K) {
    extern __shared__ __align__(16) char gsm[];
    const uint32_t smb = smem_u32(gsm);
    const GemmJobB job = (blockIdx.z == 0) ? j0 : j1;
    const int tid  = threadIdx.x;
    const int lane = tid & 31;
    const int w    = tid >> 5;
    const int wm   = w & 3;
    const int wn   = w >> 2;
    const int m0   = blockIdx.y * 128;
    const int n0   = blockIdx.x * 64;

    const bool isA = tid < 256;
    const bool stg = tid < 384;
    const int srow = isA ? (tid >> 1) : ((tid - 256) >> 1);
    const int sseg = tid & 1;
    const __nv_bfloat16* srcH = isA
        ? (Ahi + (size_t)(m0 + srow) * lda + sseg * 32)
        : (job.Bhi + (size_t)(n0 + srow) * ldb + sseg * 32);
    const __nv_bfloat16* srcL = isA
        ? (Alo + (size_t)(m0 + srow) * lda + sseg * 32)
        : (job.Blo + (size_t)(n0 + srow) * ldb + sseg * 32);
    const uint32_t dsth = (isA ? 0u : 2u * GASZ)
                        + (uint32_t)(srow * GPITCH + sseg * 32) * 2u;
    const uint32_t dstl = dsth + (uint32_t)(isA ? GASZ : GBSZ);

    auto stage = [&](int kt, int buf) {
        if (!stg) return;
        uint32_t dh = smb + (uint32_t)buf * GBUF + dsth;
        uint32_t dl = smb + (uint32_t)buf * GBUF + dstl;
        const char* sh = (const char*)(srcH + (size_t)kt * GBK);
        const char* sl = (const char*)(srcL + (size_t)kt * GBK);
#pragma unroll
        for (int q = 0; q < 4; q++) {
            CP16(dh + 16 * q, sh + 16 * q);
            CP16(dl + 16 * q, sl + 16 * q);
        }
    };

    const uint32_t aoff = (uint32_t)(((lane & 7) + ((lane >> 3) & 1) * 8) * GPITCH
                                     + (lane >> 4) * 8) * 2u;
    const uint32_t boff = (uint32_t)(((lane & 7) + ((lane >> 4) & 1) * 8) * GPITCH
                                     + ((lane >> 3) & 1) * 8) * 2u;
    const uint32_t awarp = (uint32_t)(wm * 32 * GPITCH) * 2u;
    const uint32_t bwarp = (uint32_t)(wn * 16 * GPITCH) * 2u;

    float acc[2][2][4];
#pragma unroll
    for (int mf = 0; mf < 2; mf++)
#pragma unroll
        for (int nf = 0; nf < 2; nf++)
#pragma unroll
            for (int i = 0; i < 4; i++) acc[mf][nf][i] = 0.f;

    auto compute = [&](int buf) {
        const uint32_t b0 = smb + (uint32_t)buf * GBUF;
#pragma unroll 1
        for (int pass = 0; pass < 3; pass++) {
            const uint32_t Ab = b0 + (pass == 2 ? (uint32_t)GASZ : 0u) + awarp + aoff;
            const uint32_t Bb = b0 + 2u * GASZ + (pass == 1 ? (uint32_t)GBSZ : 0u)
                              + bwarp + boff;
#pragma unroll
            for (int ks = 0; ks < 4; ks++) {
                const uint32_t ko = (uint32_t)ks * 32u;
                uint32_t a0[4], a1[4], bb[4];
                ldm_x4(a0[0], a0[1], a0[2], a0[3], Ab + ko);
                ldm_x4(a1[0], a1[1], a1[2], a1[3], Ab + ko + 16u * GPITCH * 2u);
                ldm_x4(bb[0], bb[1], bb[2], bb[3], Bb + ko);
                mma_bf16(acc[0][0], a0, bb[0], bb[1]);
                mma_bf16(acc[0][1], a0, bb[2], bb[3]);
                mma_bf16(acc[1][0], a1, bb[0], bb[1]);
                mma_bf16(acc[1][1], a1, bb[2], bb[3]);
            }
        }
    };

    const int ktiles = K / GBK;
    // prologue: stage tiles 0..NSTAGE-2 (each its own commit group)
#pragma unroll
    for (int s = 0; s < NSTAGE - 1; s++) {
        if (s < ktiles) stage(s, s);
        CP_COMMIT();
    }
    for (int it = 0; it < ktiles; it++) {
        CP_WAIT2();            // tile it's group retired (commit counting)
        __syncthreads();       // also fences buffer (it-1)%4 compute for restage
        compute(it & (NSTAGE - 1));
        int nx = it + NSTAGE - 1;
        if (nx < ktiles) stage(nx, nx & (NSTAGE - 1));
        CP_COMMIT();           // unconditional: keeps group counting uniform
    }

#pragma unroll
    for (int mf = 0; mf < 2; mf++)
#pragma unroll
        for (int nf = 0; nf < 2; nf++) {
            int m = m0 + wm * 32 + mf * 16 + (lane >> 2);
            int nc = n0 + wn * 16 + nf * 8 + (lane & 3) * 2;
            float b0v = 0.f, b1v = 0.f;
            if (job.bias) { b0v = __ldg(&job.bias[nc]); b1v = __ldg(&job.bias[nc + 1]); }
            float o00 = acc[mf][nf][0] + b0v;
            float o01 = acc[mf][nf][1] + b1v;
            float o10 = acc[mf][nf][2] + b0v;
            float o11 = acc[mf][nf][3] + b1v;
            if (job.C) {
                job.C[(size_t)m * ldc + nc]           = o00;
                job.C[(size_t)m * ldc + nc + 1]       = o01;
                job.C[(size_t)(m + 8) * ldc + nc]     = o10;
                job.C[(size_t)(m + 8) * ldc + nc + 1] = o11;
            }
            if (job.Chi) {
                __nv_bfloat16 h, l;
                split_bf16(o00, h, l);
                job.Chi[(size_t)m * ldc + nc] = h;
                job.Clo[(size_t)m * ldc + nc] = l;
                split_bf16(o01, h, l);
                job.Chi[(size_t)m * ldc + nc + 1] = h;
                job.Clo[(size_t)m * ldc + nc + 1] = l;
                split_bf16(o10, h, l);
                job.Chi[(size_t)(m + 8) * ldc + nc] = h;
                job.Clo[(size_t)(m + 8) * ldc + nc] = l;
                split_bf16(o11, h, l);
                job.Chi[(size_t)(m + 8) * ldc + nc + 1] = h;
                job.Clo[(size_t)(m + 8) * ldc + nc + 1] = l;
            }
        }
}

// ---------------------------------------------------------------------------
// K4: edge head. One warp per edge: v = relu(A1[n1]+A2[n2]); 6 dots + bias.
// ---------------------------------------------------------------------------
__global__ void edge_out_kernel(const float* __restrict__ xyzRw,
                                const float* __restrict__ xyzRb,
                                const float* __restrict__ wpqrRw,
                                const float* __restrict__ wpqrRb,
                                float* __restrict__ out) {
    int warp = (blockIdx.x * blockDim.x + threadIdx.x) >> 5;
    int lane = threadIdx.x & 31;
    if (warp >= NE) return;
    const float* r1 = g_A1 + (size_t)g_n1[warp] * FEAT;
    const float* r2 = g_A2 + (size_t)g_n2[warp] * FEAT;
    float acc[6] = {0.f, 0.f, 0.f, 0.f, 0.f, 0.f};
    for (int k = lane; k < FEAT; k += 32) {
        float v = fmaxf(r1[k] + r2[k], 0.f);
        acc[0] += v * __ldg(&xyzRw[k]);
        acc[1] += v * __ldg(&xyzRw[FEAT + k]);
        acc[2] += v * __ldg(&xyzRw[2 * FEAT + k]);
        acc[3] += v * __ldg(&wpqrRw[k]);
        acc[4] += v * __ldg(&wpqrRw[FEAT + k]);
        acc[5] += v * __ldg(&wpqrRw[2 * FEAT + k]);
    }
#pragma unroll
    for (int j = 0; j < 6; j++)
#pragma unroll
        for (int off = 16; off; off >>= 1)
            acc[j] += __shfl_xor_sync(0xffffffffu, acc[j], off);
    if (lane < 6) {
        float b = (lane < 3) ? xyzRb[lane] : wpqrRb[lane - 3];
        out[NN * 6 + warp * 6 + lane] = acc[lane] + b;
    }
}

// ---------------------------------------------------------------------------
// K5: node head. One warp per node on relu(node_hi + node_lo) (exact fp32).
// ---------------------------------------------------------------------------
__global__ void node_out_kernel(const float* __restrict__ xyzw,
                                const float* __restrict__ xyzb,
                                const float* __restrict__ wpqrw,
                                const float* __restrict__ wpqrb,
                                float* __restrict__ out) {
    int warp = (blockIdx.x * blockDim.x + threadIdx.x) >> 5;
    int lane = threadIdx.x & 31;
    if (warp >= NN) return;
    const __nv_bfloat16* rh = g_node_hi + (size_t)warp * FEAT;
    const __nv_bfloat16* rl = g_node_lo + (size_t)warp * FEAT;
    float acc[6] = {0.f, 0.f, 0.f, 0.f, 0.f, 0.f};
    for (int k = lane; k < FEAT; k += 32) {
        float v = fmaxf(__bfloat162float(rh[k]) + __bfloat162float(rl[k]), 0.f);
        acc[0] += v * __ldg(&xyzw[k]);
        acc[1] += v * __ldg(&xyzw[FEAT + k]);
        acc[2] += v * __ldg(&xyzw[2 * FEAT + k]);
        acc[3] += v * __ldg(&wpqrw[k]);
        acc[4] += v * __ldg(&wpqrw[FEAT + k]);
        acc[5] += v * __ldg(&wpqrw[2 * FEAT + k]);
    }
#pragma unroll
    for (int j = 0; j < 6; j++)
#pragma unroll
        for (int off = 16; off; off >>= 1)
            acc[j] += __shfl_xor_sync(0xffffffffu, acc[j], off);
    if (lane < 6) {
        float b = (lane < 3) ? xyzb[lane] : wpqrb[lane - 3];
        out[warp * 6 + lane] = acc[lane] + b;
    }
}

// ---------------------------------------------------------------------------
extern "C" void kernel_launch(void* const* d_in, const int* in_sizes, int n_in,
                              void* d_out, int out_size) {
    const float* x        = (const float*)d_in[0];
    const void*  ei       = d_in[1];
    const float* conv_w   = (const float*)d_in[2];
    const float* conv_b   = (const float*)d_in[3];
    const float* fc_w     = (const float*)d_in[4];
    const float* fc_b     = (const float*)d_in[5];
    const float* proj_w   = (const float*)d_in[6];
    const float* proj_b   = (const float*)d_in[7];
    const float* xyz_w    = (const float*)d_in[8];
    const float* xyz_b    = (const float*)d_in[9];
    const float* wpqr_w   = (const float*)d_in[10];
    const float* wpqr_b   = (const float*)d_in[11];
    const float* xyz_R_w  = (const float*)d_in[12];
    const float* xyz_R_b  = (const float*)d_in[13];
    const float* wpqr_R_w = (const float*)d_in[14];
    const float* wpqr_R_b = (const float*)d_in[15];
    float* out = (float*)d_out;

    float *pA1, *pA2;
    __nv_bfloat16 *pfh, *pfl, *pnh, *pnl, *pfcwh, *pfcwl, *ppwh, *ppwl;
    cudaGetSymbolAddress((void**)&pA1, g_A1);
    cudaGetSymbolAddress((void**)&pA2, g_A2);
    cudaGetSymbolAddress((void**)&pfh, g_feat_hi);
    cudaGetSymbolAddress((void**)&pfl, g_feat_lo);
    cudaGetSymbolAddress((void**)&pnh, g_node_hi);
    cudaGetSymbolAddress((void**)&pnl, g_node_lo);
    cudaGetSymbolAddress((void**)&pfcwh, g_fcw_hi);
    cudaGetSymbolAddress((void**)&pfcwl, g_fcw_lo);
    cudaGetSymbolAddress((void**)&ppwh, g_pw_hi);
    cudaGetSymbolAddress((void**)&ppwl, g_pw_lo);

    wsplit_all_kernel<<<4096, 256>>>(conv_w, fc_w, proj_w);        // #1

    cudaFuncSetAttribute(conv_mma_kernel,
                         cudaFuncAttributeMaxDynamicSharedMemorySize, SM_CONV_TOTAL);
    conv_mma_kernel<<<NN, 512, SM_CONV_TOTAL>>>(x, conv_b);        // #2

    cudaFuncSetAttribute(gemm_mma_kernel,
                         cudaFuncAttributeMaxDynamicSharedMemorySize, GSM_TOTAL);
    // fc: node = feat @ fc_w^T + fc_b  (hi/lo only)                 // #3
    {
        GemmJobB j0{pfcwh, pfcwl, fc_b, nullptr, pnh, pnl};
        gemm_mma_kernel<<<dim3(FEAT / 64, NN / 128, 1), 512, GSM_TOTAL>>>(
            pfh, pfl, CO, j0, j0, CO, FEAT, CO);
    }
    // A1 = node @ W1^T + proj_b ; A2 = node @ W2^T                  // #4 (profiled)
    {
        GemmJobB j0{ppwh, ppwl, proj_b, pA1, nullptr, nullptr};
        GemmJobB j1{ppwh + FEAT, ppwl + FEAT, nullptr, pA2, nullptr, nullptr};
        gemm_mma_kernel<<<dim3(FEAT / 64, NN / 128, 2), 512, GSM_TOTAL>>>(
            pnh, pnl, FEAT, j0, j1, 2 * FEAT, FEAT, FEAT);
    }

    edge_prep_kernel<<<1, 256>>>(ei);                              // #5
    edge_out_kernel<<<(NE * 32) / 256, 256>>>(xyz_R_w, xyz_R_b, wpqr_R_w, wpqr_R_b, out);
    node_out_kernel<<<(NN * 32) / 256, 256>>>(xyz_w, xyz_b, wpqr_w, wpqr_b, out);
}

// round 17
// speedup vs baseline: 1.0379x; 1.0379x over previous
#include <cuda_runtime.h>
#include <cuda_bf16.h>
#include <cstddef>
#include <cstdint>

// ---------------------------------------------------------------------------
// PoseNetX_LIGHT: conv7x7/s16 -> relu -> avgpool -> fc -> {node head, edge head}
// Edge GEMM algebraically factored:  edge = relu(A1[n1] + A2[n2]).
// R17: hi/lo 3-pass FUSED into one k-loop in both mma kernels — each smem
//      fragment loaded once, all three products issued from registers
//      (smem read traffic -33%; R16 showed the GEMM is L1-bandwidth bound).
// ---------------------------------------------------------------------------

#define NN 256        // nodes
#define NE 8192       // edges
#define HW 256
#define CO 512
#define KK 147        // 3*7*7
#define KPAD 160      // 10 ksteps of 16
#define KPITCH 168    // conv smem row pitch (elems)
#define FEAT 2048

// -------- scratch (no allocations allowed) --------
__device__ float g_A1[NN * FEAT];        // node @ W1^T + proj_b
__device__ float g_A2[NN * FEAT];        // node @ W2^T
__device__ int   g_n1[NE];
__device__ int   g_n2[NE];
__device__ __nv_bfloat16 g_wbf_hi[CO * KPITCH];   // conv weights hi (smem image)
__device__ __nv_bfloat16 g_wbf_lo[CO * KPITCH];   // conv weights lo
__device__ __nv_bfloat16 g_feat_hi[NN * CO];      // pooled features hi
__device__ __nv_bfloat16 g_feat_lo[NN * CO];      // pooled features lo
__device__ __nv_bfloat16 g_node_hi[NN * FEAT];    // fc output hi
__device__ __nv_bfloat16 g_node_lo[NN * FEAT];    // fc output lo
__device__ __nv_bfloat16 g_fcw_hi[FEAT * CO];     // fc_w hi
__device__ __nv_bfloat16 g_fcw_lo[FEAT * CO];     // fc_w lo
__device__ __nv_bfloat16 g_pw_hi[FEAT * 2 * FEAT];  // proj_w hi
__device__ __nv_bfloat16 g_pw_lo[FEAT * 2 * FEAT];  // proj_w lo

// -------- warp-mma helpers (sm_80+ ISA; valid on plain sm_100) --------
__device__ __forceinline__ uint32_t smem_u32(const void* p) {
    uint32_t a;
    asm("{ .reg .u64 t; cvta.to.shared.u64 t, %1; cvt.u32.u64 %0, t; }"
        : "=r"(a) : "l"(p));
    return a;
}
__device__ __forceinline__ void ldm_x4(uint32_t& r0, uint32_t& r1,
                                       uint32_t& r2, uint32_t& r3, uint32_t addr) {
    asm volatile("ldmatrix.sync.aligned.m8n8.x4.shared.b16 {%0,%1,%2,%3}, [%4];"
                 : "=r"(r0), "=r"(r1), "=r"(r2), "=r"(r3) : "r"(addr));
}
__device__ __forceinline__ void mma_bf16(float* c, const uint32_t* a,
                                         uint32_t b0, uint32_t b1) {
    asm volatile(
        "mma.sync.aligned.m16n8k16.row.col.f32.bf16.bf16.f32 "
        "{%0,%1,%2,%3}, {%4,%5,%6,%7}, {%8,%9}, {%0,%1,%2,%3};"
        : "+f"(c[0]), "+f"(c[1]), "+f"(c[2]), "+f"(c[3])
        : "r"(a[0]), "r"(a[1]), "r"(a[2]), "r"(a[3]), "r"(b0), "r"(b1));
}
#define CP16(dst, src) \
    asm volatile("cp.async.ca.shared.global [%0], [%1], 16;" \
                 :: "r"(dst), "l"(src) : "memory")
#define CP_COMMIT() asm volatile("cp.async.commit_group;" ::: "memory")
#define CP_WAIT0()  asm volatile("cp.async.wait_group 0;" ::: "memory")
#define CP_WAIT2()  asm volatile("cp.async.wait_group 2;" ::: "memory")

__device__ __forceinline__ void split_bf16(float v, __nv_bfloat16& h,
                                           __nv_bfloat16& l) {
    h = __float2bfloat16(v);
    l = __float2bfloat16(v - __bfloat162float(h));
}

// conv smem byte layout
#define SM_POOL 0
#define SM_LUT  2048
#define TILE_B  (128 * KPITCH * 2)
#define SM_AHI  4096
#define SM_ALO  (SM_AHI + TILE_B)
#define SM_BHI  (SM_ALO + TILE_B)
#define SM_BLO  (SM_BHI + TILE_B)
#define SM_CONV_TOTAL (SM_BLO + TILE_B)     // 176128 B

// ---------------------------------------------------------------------------
// K0: normalize edge_index (auto-detect int32 vs int64), n1=min, n2=max
// ---------------------------------------------------------------------------
__global__ void edge_prep_kernel(const void* __restrict__ ei_raw) {
    __shared__ int nz;
    int tid = threadIdx.x;
    if (tid == 0) nz = 0;
    __syncthreads();
    const int* w32 = (const int*)ei_raw;
    if (tid < 64 && w32[2 * tid + 1] != 0) atomicOr(&nz, 1);
    __syncthreads();
    if (nz == 0) {
        const long long* e = (const long long*)ei_raw;
        for (int i = tid; i < NE; i += 256) {
            int u = (int)e[i], v = (int)e[NE + i];
            g_n1[i] = min(u, v);
            g_n2[i] = max(u, v);
        }
    } else {
        const int* e = w32;
        for (int i = tid; i < NE; i += 256) {
            int u = e[i], v = e[NE + i];
            g_n1[i] = min(u, v);
            g_n2[i] = max(u, v);
        }
    }
}

// ---------------------------------------------------------------------------
// K1: split ALL weights (conv + fc + proj) into bf16 hi/lo in one kernel.
// ---------------------------------------------------------------------------
__global__ void wsplit_all_kernel(const float* __restrict__ conv_w,
                                  const float* __restrict__ fcw,
                                  const float* __restrict__ pw) {
    const int NCV = CO * KPAD;              // 81920
    const int NFC = FEAT * CO;              // 1048576
    const int NPW = FEAT * 2 * FEAT;        // 8388608
    for (int i = blockIdx.x * 256 + threadIdx.x; i < NCV + NFC + NPW;
         i += gridDim.x * 256) {
        if (i < NCV) {
            int ch = i / KPAD;
            int k  = i - ch * KPAD;
            float v = (k < KK) ? conv_w[(size_t)ch * KK + k] : 0.f;
            split_bf16(v, g_wbf_hi[(size_t)ch * KPITCH + k],
                       g_wbf_lo[(size_t)ch * KPITCH + k]);
        } else if (i < NCV + NFC) {
            int j = i - NCV;
            split_bf16(fcw[j], g_fcw_hi[j], g_fcw_lo[j]);
        } else {
            int j = i - NCV - NFC;
            split_bf16(pw[j], g_pw_hi[j], g_pw_lo[j]);
        }
    }
}

// ---------------------------------------------------------------------------
// K2: conv + bias + relu + avgpool via warp mma, one block per node.
// R17: fused hi/lo passes — each fragment loaded once per kstep, 3 products.
// ---------------------------------------------------------------------------
__global__ void __launch_bounds__(512, 1)
conv_mma_kernel(const float* __restrict__ x, const float* __restrict__ cbias) {
    extern __shared__ __align__(16) char smem[];
    float* pool_s = (float*)(smem + SM_POOL);
    int* kyL = (int*)(smem + SM_LUT);
    int* kxL = kyL + KPAD;
    int* cbL = kxL + KPAD;
    const uint32_t smb = smem_u32(smem);
    const int tid  = threadIdx.x;
    const int lane = tid & 31;
    const int w    = tid >> 5;
    const int wm   = w & 3;
    const int wn   = w >> 2;
    const int n    = blockIdx.x;

    pool_s[tid < 512 ? tid : 0] = 0.f;
    if (tid < KPAD) {
        if (tid < KK) {
            int ci = tid / 49;
            int r7 = tid - ci * 49;
            kyL[tid] = r7 / 7;
            kxL[tid] = r7 - (r7 / 7) * 7;
            cbL[tid] = ci * 65536;
        } else {
            kyL[tid] = -100000;
            kxL[tid] = 0;
            cbL[tid] = 0;
        }
    }

    const uint32_t aoff = (uint32_t)(((lane & 7) + ((lane >> 3) & 1) * 8) * KPITCH
                                     + (lane >> 4) * 8) * 2u;
    const uint32_t boff = (uint32_t)(((lane & 7) + ((lane >> 4) & 1) * 8) * KPITCH
                                     + ((lane >> 3) & 1) * 8) * 2u;

    const float* xb = x + (size_t)n * (3 * HW * HW);

    for (int half = 0; half < 2; half++) {
        __syncthreads();
        for (int e = tid; e < 128 * KPAD; e += 512) {
            int r = e / KPAD;
            int k = e - r * KPAD;
            int p  = half * 128 + r;
            int oy = p >> 4, ox = p & 15;
            int iy = oy * 16 - 3 + kyL[k];
            int ix = ox * 16 - 3 + kxL[k];
            float v = 0.f;
            if ((unsigned)iy < 256u && (unsigned)ix < 256u)
                v = __ldg(&xb[cbL[k] + iy * 256 + ix]);
            __nv_bfloat16 hi, lo;
            split_bf16(v, hi, lo);
            uint32_t o = (uint32_t)(r * KPITCH + k) * 2u;
            *(__nv_bfloat16*)(smem + SM_BHI + o) = hi;
            *(__nv_bfloat16*)(smem + SM_BLO + o) = lo;
        }

        for (int mt = 0; mt < 4; mt++) {
            __syncthreads();
            {
                const char* srcH = (const char*)(g_wbf_hi + (size_t)mt * 128 * KPITCH);
                const char* srcL = (const char*)(g_wbf_lo + (size_t)mt * 128 * KPITCH);
                const int cnt = 128 * KPITCH * 2 / 16;
                for (int i = tid; i < cnt; i += 512) {
                    CP16(smb + SM_AHI + 16 * i, srcH + 16 * i);
                    CP16(smb + SM_ALO + 16 * i, srcL + 16 * i);
                }
                CP_COMMIT();
                CP_WAIT0();
            }
            __syncthreads();

            float acc[2][4][4];
#pragma unroll
            for (int mf = 0; mf < 2; mf++)
#pragma unroll
                for (int nf = 0; nf < 4; nf++)
#pragma unroll
                    for (int i = 0; i < 4; i++) acc[mf][nf][i] = 0.f;

            const uint32_t awarp = (uint32_t)(wm * 32 * KPITCH) * 2u;
            const uint32_t bwarp = (uint32_t)(wn * 32 * KPITCH) * 2u;
            const uint32_t Ah = smb + SM_AHI + awarp + aoff;
            const uint32_t Al = smb + SM_ALO + awarp + aoff;
            const uint32_t Bh = smb + SM_BHI + bwarp + boff;
            const uint32_t Bl = smb + SM_BLO + bwarp + boff;
#pragma unroll
            for (int ks = 0; ks < 10; ks++) {
                const uint32_t ko  = (uint32_t)ks * 32u;
                const uint32_t ro  = 16u * KPITCH * 2u;
                uint32_t ah[2][4], al[2][4], bh[4][2], bl[4][2];
                ldm_x4(ah[0][0], ah[0][1], ah[0][2], ah[0][3], Ah + ko);
                ldm_x4(ah[1][0], ah[1][1], ah[1][2], ah[1][3], Ah + ko + ro);
                ldm_x4(al[0][0], al[0][1], al[0][2], al[0][3], Al + ko);
                ldm_x4(al[1][0], al[1][1], al[1][2], al[1][3], Al + ko + ro);
                ldm_x4(bh[0][0], bh[0][1], bh[1][0], bh[1][1], Bh + ko);
                ldm_x4(bh[2][0], bh[2][1], bh[3][0], bh[3][1], Bh + ko + ro);
                ldm_x4(bl[0][0], bl[0][1], bl[1][0], bl[1][1], Bl + ko);
                ldm_x4(bl[2][0], bl[2][1], bl[3][0], bl[3][1], Bl + ko + ro);
#pragma unroll
                for (int mf = 0; mf < 2; mf++)
#pragma unroll
                    for (int nf = 0; nf < 4; nf++) {
                        mma_bf16(acc[mf][nf], ah[mf], bh[nf][0], bh[nf][1]);
                        mma_bf16(acc[mf][nf], ah[mf], bl[nf][0], bl[nf][1]);
                        mma_bf16(acc[mf][nf], al[mf], bh[nf][0], bh[nf][1]);
                    }
            }

#pragma unroll
            for (int mf = 0; mf < 2; mf++) {
                int ch = mt * 128 + wm * 32 + mf * 16 + (lane >> 2);
                float b0 = __ldg(&cbias[ch]);
                float b1 = __ldg(&cbias[ch + 8]);
                float p0 = 0.f, p1 = 0.f;
#pragma unroll
                for (int nf = 0; nf < 4; nf++) {
                    p0 += fmaxf(acc[mf][nf][0] + b0, 0.f)
                        + fmaxf(acc[mf][nf][1] + b0, 0.f);
                    p1 += fmaxf(acc[mf][nf][2] + b1, 0.f)
                        + fmaxf(acc[mf][nf][3] + b1, 0.f);
                }
                p0 += __shfl_xor_sync(0xffffffffu, p0, 1);
                p0 += __shfl_xor_sync(0xffffffffu, p0, 2);
                p1 += __shfl_xor_sync(0xffffffffu, p1, 1);
                p1 += __shfl_xor_sync(0xffffffffu, p1, 2);
                if ((lane & 3) == 0) {
                    int c0 = mt * 128 + wm * 32 + mf * 16 + (lane >> 2);
                    atomicAdd(&pool_s[c0], p0);
                    atomicAdd(&pool_s[c0 + 8], p1);
                }
            }
        }
    }

    __syncthreads();
    {
        float v = pool_s[tid] * (1.0f / 256.0f);
        __nv_bfloat16 hi, lo;
        split_bf16(v, hi, lo);
        g_feat_hi[n * CO + tid] = hi;
        g_feat_lo[n * CO + tid] = lo;
    }
}

// ---------------------------------------------------------------------------
// K3: NT GEMM via bf16 mma, fused hi/lo (each fragment loaded once).
// 4-stage cp.async ring. Block 128M x 64N, 512 threads. K%64==0.
// ---------------------------------------------------------------------------
struct GemmJobB {
    const __nv_bfloat16* Bhi;
    const __nv_bfloat16* Blo;
    const float* bias;
    float* C;             // optional fp32 output
    __nv_bfloat16* Chi;   // optional hi/lo outputs
    __nv_bfloat16* Clo;
};

#define GBK 64
#define GPITCH 72
#define GASZ (128 * GPITCH * 2)
#define GBSZ (64 * GPITCH * 2)
#define GBUF (2 * GASZ + 2 * GBSZ)         // 55296 B
#define NSTAGE 4
#define GSM_TOTAL (NSTAGE * GBUF)          // 221184 B

__global__ void __launch_bounds__(512, 1)
gemm_mma_kernel(const __nv_bfloat16* __restrict__ Ahi,
                const __nv_bfloat16* __restrict__ Alo, int lda,
                GemmJobB j0, GemmJobB j1, int ldb, int ldc, int K) {
    extern __shared__ __align__(16) char gsm[];
    const uint32_t smb = smem_u32(gsm);
    const GemmJobB job = (blockIdx.z == 0) ? j0 : j1;
    const int tid  = threadIdx.x;
    const int lane = tid & 31;
    const int w    = tid >> 5;
    const int wm   = w & 3;
    const int wn   = w >> 2;
    const int m0   = blockIdx.y * 128;
    const int n0   = blockIdx.x * 64;

    const bool isA = tid < 256;
    const bool stg = tid < 384;
    const int srow = isA ? (tid >> 1) : ((tid - 256) >> 1);
    const int sseg = tid & 1;
    const __nv_bfloat16* srcH = isA
        ? (Ahi + (size_t)(m0 + srow) * lda + sseg * 32)
        : (job.Bhi + (size_t)(n0 + srow) * ldb + sseg * 32);
    const __nv_bfloat16* srcL = isA
        ? (Alo + (size_t)(m0 + srow) * lda + sseg * 32)
        : (job.Blo + (size_t)(n0 + srow) * ldb + sseg * 32);
    const uint32_t dsth = (isA ? 0u : 2u * GASZ)
                        + (uint32_t)(srow * GPITCH + sseg * 32) * 2u;
    const uint32_t dstl = dsth + (uint32_t)(isA ? GASZ : GBSZ);

    auto stage = [&](int kt, int buf) {
        if (!stg) return;
        uint32_t dh = smb + (uint32_t)buf * GBUF + dsth;
        uint32_t dl = smb + (uint32_t)buf * GBUF + dstl;
        const char* sh = (const char*)(srcH + (size_t)kt * GBK);
        const char* sl = (const char*)(srcL + (size_t)kt * GBK);
#pragma unroll
        for (int q = 0; q < 4; q++) {
            CP16(dh + 16 * q, sh + 16 * q);
            CP16(dl + 16 * q, sl + 16 * q);
        }
    };

    const uint32_t aoff = (uint32_t)(((lane & 7) + ((lane >> 3) & 1) * 8) * GPITCH
                                     + (lane >> 4) * 8) * 2u;
    const uint32_t boff = (uint32_t)(((lane & 7) + ((lane >> 4) & 1) * 8) * GPITCH
                                     + ((lane >> 3) & 1) * 8) * 2u;
    const uint32_t awarp = (uint32_t)(wm * 32 * GPITCH) * 2u;
    const uint32_t bwarp = (uint32_t)(wn * 16 * GPITCH) * 2u;

    float acc[2][2][4];
#pragma unroll
    for (int mf = 0; mf < 2; mf++)
#pragma unroll
        for (int nf = 0; nf < 2; nf++)
#pragma unroll
            for (int i = 0; i < 4; i++) acc[mf][nf][i] = 0.f;

    auto compute = [&](int buf) {
        const uint32_t b0 = smb + (uint32_t)buf * GBUF;
        const uint32_t Ah = b0 + awarp + aoff;
        const uint32_t Al = b0 + GASZ + awarp + aoff;
        const uint32_t Bh = b0 + 2u * GASZ + bwarp + boff;
        const uint32_t Bl = b0 + 2u * GASZ + GBSZ + bwarp + boff;
        const uint32_t ro = 16u * GPITCH * 2u;
#pragma unroll
        for (int ks = 0; ks < 4; ks++) {
            const uint32_t ko = (uint32_t)ks * 32u;
            uint32_t ah0[4], ah1[4], al0[4], al1[4], bh[4], bl[4];
            ldm_x4(ah0[0], ah0[1], ah0[2], ah0[3], Ah + ko);
            ldm_x4(ah1[0], ah1[1], ah1[2], ah1[3], Ah + ko + ro);
            ldm_x4(al0[0], al0[1], al0[2], al0[3], Al + ko);
            ldm_x4(al1[0], al1[1], al1[2], al1[3], Al + ko + ro);
            ldm_x4(bh[0], bh[1], bh[2], bh[3], Bh + ko);
            ldm_x4(bl[0], bl[1], bl[2], bl[3], Bl + ko);
            mma_bf16(acc[0][0], ah0, bh[0], bh[1]);
            mma_bf16(acc[0][1], ah0, bh[2], bh[3]);
            mma_bf16(acc[1][0], ah1, bh[0], bh[1]);
            mma_bf16(acc[1][1], ah1, bh[2], bh[3]);
            mma_bf16(acc[0][0], ah0, bl[0], bl[1]);
            mma_bf16(acc[0][1], ah0, bl[2], bl[3]);
            mma_bf16(acc[1][0], ah1, bl[0], bl[1]);
            mma_bf16(acc[1][1], ah1, bl[2], bl[3]);
            mma_bf16(acc[0][0], al0, bh[0], bh[1]);
            mma_bf16(acc[0][1], al0, bh[2], bh[3]);
            mma_bf16(acc[1][0], al1, bh[0], bh[1]);
            mma_bf16(acc[1][1], al1, bh[2], bh[3]);
        }
    };

    const int ktiles = K / GBK;
#pragma unroll
    for (int s = 0; s < NSTAGE - 1; s++) {
        if (s < ktiles) stage(s, s);
        CP_COMMIT();
    }
    for (int it = 0; it < ktiles; it++) {
        CP_WAIT2();
        __syncthreads();
        compute(it & (NSTAGE - 1));
        int nx = it + NSTAGE - 1;
        if (nx < ktiles) stage(nx, nx & (NSTAGE - 1));
        CP_COMMIT();
    }

#pragma unroll
    for (int mf = 0; mf < 2; mf++)
#pragma unroll
        for (int nf = 0; nf < 2; nf++) {
            int m = m0 + wm * 32 + mf * 16 + (lane >> 2);
            int nc = n0 + wn * 16 + nf * 8 + (lane & 3) * 2;
            float b0v = 0.f, b1v = 0.f;
            if (job.bias) { b0v = __ldg(&job.bias[nc]); b1v = __ldg(&job.bias[nc + 1]); }
            float o00 = acc[mf][nf][0] + b0v;
            float o01 = acc[mf][nf][1] + b1v;
            float o10 = acc[mf][nf][2] + b0v;
            float o11 = acc[mf][nf][3] + b1v;
            if (job.C) {
                job.C[(size_t)m * ldc + nc]           = o00;
                job.C[(size_t)m * ldc + nc + 1]       = o01;
                job.C[(size_t)(m + 8) * ldc + nc]     = o10;
                job.C[(size_t)(m + 8) * ldc + nc + 1] = o11;
            }
            if (job.Chi) {
                __nv_bfloat16 h, l;
                split_bf16(o00, h, l);
                job.Chi[(size_t)m * ldc + nc] = h;
                job.Clo[(size_t)m * ldc + nc] = l;
                split_bf16(o01, h, l);
                job.Chi[(size_t)m * ldc + nc + 1] = h;
                job.Clo[(size_t)m * ldc + nc + 1] = l;
                split_bf16(o10, h, l);
                job.Chi[(size_t)(m + 8) * ldc + nc] = h;
                job.Clo[(size_t)(m + 8) * ldc + nc] = l;
                split_bf16(o11, h, l);
                job.Chi[(size_t)(m + 8) * ldc + nc + 1] = h;
                job.Clo[(size_t)(m + 8) * ldc + nc + 1] = l;
            }
        }
}

// ---------------------------------------------------------------------------
// K4: edge head. One warp per edge: v = relu(A1[n1]+A2[n2]); 6 dots + bias.
// ---------------------------------------------------------------------------
__global__ void edge_out_kernel(const float* __restrict__ xyzRw,
                                const float* __restrict__ xyzRb,
                                const float* __restrict__ wpqrRw,
                                const float* __restrict__ wpqrRb,
                                float* __restrict__ out) {
    int warp = (blockIdx.x * blockDim.x + threadIdx.x) >> 5;
    int lane = threadIdx.x & 31;
    if (warp >= NE) return;
    const float* r1 = g_A1 + (size_t)g_n1[warp] * FEAT;
    const float* r2 = g_A2 + (size_t)g_n2[warp] * FEAT;
    float acc[6] = {0.f, 0.f, 0.f, 0.f, 0.f, 0.f};
    for (int k = lane; k < FEAT; k += 32) {
        float v = fmaxf(r1[k] + r2[k], 0.f);
        acc[0] += v * __ldg(&xyzRw[k]);
        acc[1] += v * __ldg(&xyzRw[FEAT + k]);
        acc[2] += v * __ldg(&xyzRw[2 * FEAT + k]);
        acc[3] += v * __ldg(&wpqrRw[k]);
        acc[4] += v * __ldg(&wpqrRw[FEAT + k]);
        acc[5] += v * __ldg(&wpqrRw[2 * FEAT + k]);
    }
#pragma unroll
    for (int j = 0; j < 6; j++)
#pragma unroll
        for (int off = 16; off; off >>= 1)
            acc[j] += __shfl_xor_sync(0xffffffffu, acc[j], off);
    if (lane < 6) {
        float b = (lane < 3) ? xyzRb[lane] : wpqrRb[lane - 3];
        out[NN * 6 + warp * 6 + lane] = acc[lane] + b;
    }
}

// ---------------------------------------------------------------------------
// K5: node head. One warp per node on relu(node_hi + node_lo) (exact fp32).
// ---------------------------------------------------------------------------
__global__ void node_out_kernel(const float* __restrict__ xyzw,
                                const float* __restrict__ xyzb,
                                const float* __restrict__ wpqrw,
                                const float* __restrict__ wpqrb,
                                float* __restrict__ out) {
    int warp = (blockIdx.x * blockDim.x + threadIdx.x) >> 5;
    int lane = threadIdx.x & 31;
    if (warp >= NN) return;
    const __nv_bfloat16* rh = g_node_hi + (size_t)warp * FEAT;
    const __nv_bfloat16* rl = g_node_lo + (size_t)warp * FEAT;
    float acc[6] = {0.f, 0.f, 0.f, 0.f, 0.f, 0.f};
    for (int k = lane; k < FEAT; k += 32) {
        float v = fmaxf(__bfloat162float(rh[k]) + __bfloat162float(rl[k]), 0.f);
        acc[0] += v * __ldg(&xyzw[k]);
        acc[1] += v * __ldg(&xyzw[FEAT + k]);
        acc[2] += v * __ldg(&xyzw[2 * FEAT + k]);
        acc[3] += v * __ldg(&wpqrw[k]);
        acc[4] += v * __ldg(&wpqrw[FEAT + k]);
        acc[5] += v * __ldg(&wpqrw[2 * FEAT + k]);
    }
#pragma unroll
    for (int j = 0; j < 6; j++)
#pragma unroll
        for (int off = 16; off; off >>= 1)
            acc[j] += __shfl_xor_sync(0xffffffffu, acc[j], off);
    if (lane < 6) {
        float b = (lane < 3) ? xyzb[lane] : wpqrb[lane - 3];
        out[warp * 6 + lane] = acc[lane] + b;
    }
}

// ---------------------------------------------------------------------------
extern "C" void kernel_launch(void* const* d_in, const int* in_sizes, int n_in,
                              void* d_out, int out_size) {
    const float* x        = (const float*)d_in[0];
    const void*  ei       = d_in[1];
    const float* conv_w   = (const float*)d_in[2];
    const float* conv_b   = (const float*)d_in[3];
    const float* fc_w     = (const float*)d_in[4];
    const float* fc_b     = (const float*)d_in[5];
    const float* proj_w   = (const float*)d_in[6];
    const float* proj_b   = (const float*)d_in[7];
    const float* xyz_w    = (const float*)d_in[8];
    const float* xyz_b    = (const float*)d_in[9];
    const float* wpqr_w   = (const float*)d_in[10];
    const float* wpqr_b   = (const float*)d_in[11];
    const float* xyz_R_w  = (const float*)d_in[12];
    const float* xyz_R_b  = (const float*)d_in[13];
    const float* wpqr_R_w = (const float*)d_in[14];
    const float* wpqr_R_b = (const float*)d_in[15];
    float* out = (float*)d_out;

    float *pA1, *pA2;
    __nv_bfloat16 *pfh, *pfl, *pnh, *pnl, *pfcwh, *pfcwl, *ppwh, *ppwl;
    cudaGetSymbolAddress((void**)&pA1, g_A1);
    cudaGetSymbolAddress((void**)&pA2, g_A2);
    cudaGetSymbolAddress((void**)&pfh, g_feat_hi);
    cudaGetSymbolAddress((void**)&pfl, g_feat_lo);
    cudaGetSymbolAddress((void**)&pnh, g_node_hi);
    cudaGetSymbolAddress((void**)&pnl, g_node_lo);
    cudaGetSymbolAddress((void**)&pfcwh, g_fcw_hi);
    cudaGetSymbolAddress((void**)&pfcwl, g_fcw_lo);
    cudaGetSymbolAddress((void**)&ppwh, g_pw_hi);
    cudaGetSymbolAddress((void**)&ppwl, g_pw_lo);

    wsplit_all_kernel<<<4096, 256>>>(conv_w, fc_w, proj_w);        // #1

    cudaFuncSetAttribute(conv_mma_kernel,
                         cudaFuncAttributeMaxDynamicSharedMemorySize, SM_CONV_TOTAL);
    conv_mma_kernel<<<NN, 512, SM_CONV_TOTAL>>>(x, conv_b);        // #2

    cudaFuncSetAttribute(gemm_mma_kernel,
                         cudaFuncAttributeMaxDynamicSharedMemorySize, GSM_TOTAL);
    // fc: node = feat @ fc_w^T + fc_b  (hi/lo only)                 // #3
    {
        GemmJobB j0{pfcwh, pfcwl, fc_b, nullptr, pnh, pnl};
        gemm_mma_kernel<<<dim3(FEAT / 64, NN / 128, 1), 512, GSM_TOTAL>>>(
            pfh, pfl, CO, j0, j0, CO, FEAT, CO);
    }
    // A1 = node @ W1^T + proj_b ; A2 = node @ W2^T                  // #4 (profiled)
    {
        GemmJobB j0{ppwh, ppwl, proj_b, pA1, nullptr, nullptr};
        GemmJobB j1{ppwh + FEAT, ppwl + FEAT, nullptr, pA2, nullptr, nullptr};
        gemm_mma_kernel<<<dim3(FEAT / 64, NN / 128, 2), 512, GSM_TOTAL>>>(
            pnh, pnl, FEAT, j0, j1, 2 * FEAT, FEAT, FEAT);
    }

    edge_prep_kernel<<<1, 256>>>(ei);                              // #5
    edge_out_kernel<<<(NE * 32) / 256, 256>>>(xyz_R_w, xyz_R_b, wpqr_R_w, wpqr_R_b, out);
    node_out_kernel<<<(NN * 32) / 256, 256>>>(xyz_w, xyz_b, wpqr_w, wpqr_b, out);
}